// round 2
// baseline (speedup 1.0000x reference)
#include <cuda_runtime.h>
#include <math.h>

// LMLLoss: x [2048, 32000] f32, y [2048] i32 -> scalar f32
//
// loss = mean_b( -log( sigmoid(xn_{b,y_b} + nu_b) + 1e-8 ) )
// where xn = L2-normalized row, nu_b solves sum_j sigmoid(xn_{b,j} + nu_b) = 5.
//
// Since |xn| <= ~0.03 and nu ~ -8.76, all t = exp(xn+nu) <= ~2e-4, so
// sigmoid(z) = t - t^2 + t^3 - O(t^4)  (trunc err ~5e-12 relative).
// With a = e^nu, E_i = exp(xn_i):  sum sigmoid = a*S1 - a^2*S2 + a^3*S3,
// S1=sum E, S2=sum E^2, S3=sum E^3.  Solve the scalar cubic for a by Newton.
// This replaces 60 bisection passes with a single exp pass over the data.

#define NC 32000
#define NB 2048
#define NT 1024
#define NV (NC / 4)        // 8000 float4 per row
#define NJ 8               // ceil(8000 / 1024)

__device__ float g_row_loss[NB];

__device__ __forceinline__ float warp_sum(float v) {
#pragma unroll
    for (int o = 16; o > 0; o >>= 1) v += __shfl_xor_sync(0xffffffffu, v, o);
    return v;
}

// Block-wide sum over NT=1024 threads (32 warps). red must hold 32 floats.
__device__ __forceinline__ float block_sum(float v, float* red) {
    int lane = threadIdx.x & 31;
    int w = threadIdx.x >> 5;
    v = warp_sum(v);
    if (lane == 0) red[w] = v;
    __syncthreads();
    if (w == 0) {
        float t = red[lane];
        t = warp_sum(t);
        if (lane == 0) red[0] = t;
    }
    __syncthreads();
    float r = red[0];
    __syncthreads();   // protect red[] for reuse by the next reduction
    return r;
}

__global__ __launch_bounds__(NT, 1)
void lml_row_kernel(const float* __restrict__ x, const int* __restrict__ y) {
    __shared__ float red[32];
    const int row = blockIdx.x;
    const float4* __restrict__ xr =
        reinterpret_cast<const float4*>(x) + (size_t)row * NV;

    // ---- Pass 1: load row into registers, fused sum of squares ----
    float4 vr[NJ];
    float ss = 0.0f;
#pragma unroll
    for (int j = 0; j < NJ; ++j) {
        int i = threadIdx.x + j * NT;
        if (i < NV) {
            float4 v = __ldg(&xr[i]);
            vr[j] = v;
            ss = fmaf(v.x, v.x, ss);
            ss = fmaf(v.y, v.y, ss);
            ss = fmaf(v.z, v.z, ss);
            ss = fmaf(v.w, v.w, ss);
        }
    }
    ss = block_sum(ss, red);
    const float inv = 1.0f / fmaxf(sqrtf(ss), 1e-12f);   // TAU = 1

    // ---- Pass 2: E = exp(xn), accumulate S1, S2, S3 from registers ----
    float s1 = 0.0f, s2 = 0.0f, s3 = 0.0f;
#pragma unroll
    for (int j = 0; j < NJ; ++j) {
        int i = threadIdx.x + j * NT;
        if (i < NV) {
            float4 v = vr[j];
            float e0 = __expf(v.x * inv);
            float e1 = __expf(v.y * inv);
            float e2 = __expf(v.z * inv);
            float e3 = __expf(v.w * inv);
            s1 += (e0 + e1) + (e2 + e3);
            float q0 = e0 * e0, q1 = e1 * e1, q2 = e2 * e2, q3 = e3 * e3;
            s2 += (q0 + q1) + (q2 + q3);
            s3 += (q0 * e0 + q1 * e1) + (q2 * e2 + q3 * e3);
        }
    }
    s1 = block_sum(s1, red);
    s2 = block_sum(s2, red);
    s3 = block_sum(s3, red);

    // ---- Scalar solve + per-row loss (one thread) ----
    if (threadIdx.x == 0) {
        // Solve a*S1 - a^2*S2 + a^3*S3 = 5 for a = e^nu.  Monotone near root,
        // Newton from a0 = 5/S1 converges in ~2 steps; do 6 for safety.
        float a = 5.0f / s1;
#pragma unroll
        for (int it = 0; it < 6; ++it) {
            float f  = a * (s1 - a * (s2 - a * s3)) - 5.0f;
            float fp = s1 - a * (2.0f * s2 - 3.0f * a * s3);
            a -= f / fp;
        }
        int yi = y[row];
        float xny = x[(size_t)row * NC + yi] * inv;
        float t = a * __expf(xny);          // t = exp(xn_y + nu)
        float p = t / (1.0f + t);           // exact sigmoid for the gathered elem
        g_row_loss[row] = -logf(p + 1e-8f);
    }
}

__global__ __launch_bounds__(NT, 1)
void lml_reduce_kernel(float* __restrict__ out) {
    __shared__ float red[32];
    float v = g_row_loss[threadIdx.x] + g_row_loss[threadIdx.x + NT];
    v = block_sum(v, red);
    if (threadIdx.x == 0) out[0] = v * (1.0f / (float)NB);
}

extern "C" void kernel_launch(void* const* d_in, const int* in_sizes, int n_in,
                              void* d_out, int out_size) {
    const float* x = (const float*)d_in[0];
    const int*   y = (const int*)d_in[1];
    float*     out = (float*)d_out;
    (void)in_sizes; (void)n_in; (void)out_size;

    lml_row_kernel<<<NB, NT>>>(x, y);
    lml_reduce_kernel<<<1, NT>>>(out);
}

// round 3
// speedup vs baseline: 1.1126x; 1.1126x over previous
#include <cuda_runtime.h>
#include <math.h>

// LMLLoss: x [2048, 32000] f32, y [2048] i32 -> scalar f32
//
// Math (from R0, validated rel_err=0.0):
//   sigmoid(xn_i + nu) with |xn|<=~0.03, nu~-8.76  =>  t = a*E_i, a=e^nu, E_i=exp(xn_i),
//   sum sigmoid = a*S1 - a^2*S2 + a^3*S3  (cubic series, trunc err ~5e-12 rel).
//   Newton on the scalar cubic replaces the reference's 60 bisection passes.
//
// R2 structure: persistent CTAs (one per SM), cp.async prefetch of row r+1 into
// SMEM overlapped with the exp pass of row r (held in registers). Final mean is
// folded into the same kernel via a deterministic last-CTA reduction.

#define NC   32000
#define NB   2048
#define NT   1024
#define NV   (NC / 4)      // 8000 float4 per row
#define NJ   8             // ceil(NV / NT)
#define GRID 152           // GB300 SM count; occ=1 (128KB smem/CTA)

__device__ float g_row_loss[NB];
__device__ unsigned int g_done;   // zero-init; self-resets each launch

__device__ __forceinline__ float warp_sum(float v) {
#pragma unroll
    for (int o = 16; o > 0; o >>= 1) v += __shfl_xor_sync(0xffffffffu, v, o);
    return v;
}

__device__ __forceinline__ float block_sum(float v, float* red) {
    int lane = threadIdx.x & 31, w = threadIdx.x >> 5;
    v = warp_sum(v);
    if (lane == 0) red[w] = v;
    __syncthreads();
    if (w == 0) {
        float t = warp_sum(red[lane]);
        if (lane == 0) red[0] = t;
    }
    __syncthreads();
    float r = red[0];
    __syncthreads();
    return r;
}

struct F3 { float a, b, c; };
// Fused 3-way block reduction: one barrier round-trip instead of three.
__device__ __forceinline__ F3 block_sum3(float a, float b, float c, float* red) {
    int lane = threadIdx.x & 31, w = threadIdx.x >> 5;
    a = warp_sum(a); b = warp_sum(b); c = warp_sum(c);
    if (lane == 0) { red[w] = a; red[32 + w] = b; red[64 + w] = c; }
    __syncthreads();
    if (w == 0) {
        float t0 = warp_sum(red[lane]);
        float t1 = warp_sum(red[32 + lane]);
        float t2 = warp_sum(red[64 + lane]);
        if (lane == 0) { red[0] = t0; red[32] = t1; red[64] = t2; }
    }
    __syncthreads();
    F3 r; r.a = red[0]; r.b = red[32]; r.c = red[64];
    __syncthreads();
    return r;
}

__device__ __forceinline__ void cp_async16(unsigned int saddr, const void* gptr) {
    asm volatile("cp.async.cg.shared.global [%0], [%1], 16;\n"
                 :: "r"(saddr), "l"(gptr));
}

__global__ __launch_bounds__(NT, 1)
void lml_kernel(const float* __restrict__ x, const int* __restrict__ y,
                float* __restrict__ out) {
    extern __shared__ float sbuf[];            // NC floats (128000 B)
    __shared__ float red[96];
    __shared__ unsigned int s_last;
    const int tid = threadIdx.x;
    const unsigned int sbase = (unsigned int)__cvta_generic_to_shared(sbuf);

    // ---- prologue: prefetch first row into smem ----
    {
        const float4* src = reinterpret_cast<const float4*>(x)
                            + (size_t)blockIdx.x * NV;
#pragma unroll
        for (int j = 0; j < NJ; ++j) {
            int i = tid + j * NT;
            if (i < NV) cp_async16(sbase + i * 16, src + i);
        }
        asm volatile("cp.async.commit_group;\n");
    }

    for (int row = blockIdx.x; row < NB; row += GRID) {
        const int yi = __ldg(&y[row]);          // issued early, hides latency

        asm volatile("cp.async.wait_group 0;\n");
        __syncthreads();                        // row r data visible in smem

        // ---- smem -> regs copy, fused sum of squares ----
        float4 vr[NJ];
        float ss = 0.0f;
        const float4* s4 = reinterpret_cast<const float4*>(sbuf);
#pragma unroll
        for (int j = 0; j < NJ; ++j) {
            int i = tid + j * NT;
            if (i < NV) {
                float4 v = s4[i];
                vr[j] = v;
                ss = fmaf(v.x, v.x, fmaf(v.y, v.y,
                     fmaf(v.z, v.z, fmaf(v.w, v.w, ss))));
            }
        }
        const float xy = (tid == 0) ? sbuf[yi] : 0.0f;  // gather before overwrite

        ss = block_sum(ss, red);                // barrier => all smem reads retired
        const float inv = rsqrtf(fmaxf(ss, 1e-24f));    // TAU = 1

        // ---- issue prefetch of row r+GRID (overlaps with exp pass below) ----
        {
            int nrow = row + GRID;
            if (nrow < NB) {
                const float4* src = reinterpret_cast<const float4*>(x)
                                    + (size_t)nrow * NV;
#pragma unroll
                for (int j = 0; j < NJ; ++j) {
                    int i = tid + j * NT;
                    if (i < NV) cp_async16(sbase + i * 16, src + i);
                }
            }
            asm volatile("cp.async.commit_group;\n");
        }

        // ---- exp pass from registers: S1, S2, S3 ----
        float s1 = 0.0f, s2 = 0.0f, s3 = 0.0f;
#pragma unroll
        for (int j = 0; j < NJ; ++j) {
            int i = tid + j * NT;
            if (i < NV) {
                float4 v = vr[j];
                float e0 = __expf(v.x * inv), e1 = __expf(v.y * inv);
                float e2 = __expf(v.z * inv), e3 = __expf(v.w * inv);
                s1 += (e0 + e1) + (e2 + e3);
                float q0 = e0 * e0, q1 = e1 * e1, q2 = e2 * e2, q3 = e3 * e3;
                s2 += (q0 + q1) + (q2 + q3);
                s3 += (q0 * e0 + q1 * e1) + (q2 * e2 + q3 * e3);
            }
        }
        F3 s = block_sum3(s1, s2, s3, red);

        if (tid == 0) {
            // Newton on a*S1 - a^2*S2 + a^3*S3 = 5, a0 = 5/S1
            float a = 5.0f / s.a;
#pragma unroll
            for (int it = 0; it < 6; ++it) {
                float f  = a * (s.a - a * (s.b - a * s.c)) - 5.0f;
                float fp = s.a - a * (2.0f * s.b - 3.0f * a * s.c);
                a -= f / fp;
            }
            float t = a * __expf(xy * inv);     // exact sigmoid on gathered elem
            float p = t / (1.0f + t);
            g_row_loss[row] = -logf(p + 1e-8f);
        }
    }

    // ---- deterministic last-CTA mean (replaces second launch) ----
    if (tid == 0) {
        __threadfence();                         // release g_row_loss writes
        unsigned int old = atomicAdd(&g_done, 1u);
        s_last = (old == GRID - 1) ? 1u : 0u;
    }
    __syncthreads();
    if (s_last) {
        __threadfence();                         // acquire
        float v = __ldcg(&g_row_loss[tid]) + __ldcg(&g_row_loss[tid + NT]);
        v = block_sum(v, red);
        if (tid == 0) {
            out[0] = v * (1.0f / (float)NB);
            g_done = 0;                          // reset for graph replay
        }
    }
}

extern "C" void kernel_launch(void* const* d_in, const int* in_sizes, int n_in,
                              void* d_out, int out_size) {
    const float* x = (const float*)d_in[0];
    const int*   y = (const int*)d_in[1];
    float*     out = (float*)d_out;
    (void)in_sizes; (void)n_in; (void)out_size;

    cudaFuncSetAttribute(lml_kernel,
                         cudaFuncAttributeMaxDynamicSharedMemorySize, NC * 4);
    lml_kernel<<<GRID, NT, NC * 4>>>(x, y, out);
}